// round 7
// baseline (speedup 1.0000x reference)
#include <cuda_runtime.h>
#include <cstdint>

// Fixed problem shapes
#define BB 8
#define CC 3
#define HH 720
#define WW 1280
#define HWP (HH * WW)          // 921600

// Tiling
#define TW 64                  // tile width  (1280 / 64 = 20)
#define TH 20                  // tile height (720 / 20 = 36)
#define R  8                   // halo radius; aligned vector staging needs R % 4 == 0
#define SW (TW + 2 * R)        // 80 texels per tile row
#define SH (TH + 2 * R)        // 36 texel rows
#define PITCHT 81              // texel pitch: 81 % 8 == 1 -> bank group = (ly+lx) mod 8
#define NTHREADS 320           // 20 rows x 16 thread-cols, 4 px/thread

__global__ __launch_bounds__(NTHREADS)
void backwarp_texel(const float* __restrict__ img,
                    const float* __restrict__ flow,
                    float* __restrict__ out) {
    __shared__ float4 smT[SH * PITCHT];   // 36*81*16 = 46656 B  (< 48KB static)

    const int tx0 = blockIdx.x * TW;
    const int ty0 = blockIdx.y * TH;
    const int b   = blockIdx.z;
    const int tid = threadIdx.x;

    const float* imb = img + (size_t)b * CC * HWP;
    const float* im0 = imb;
    const float* im1 = imb + HWP;
    const float* im2 = imb + 2 * HWP;

    // ---- Stage tile + halo as float4 texels (c0,c1,c2,0) ----
    const bool xint = (tx0 >= R) && (tx0 + TW + R <= WW);
    if (xint) {
        // vectorized: 4 texels per iteration, aligned float4 global loads
        #pragma unroll 1
        for (int g = tid; g < SH * (SW / 4); g += NTHREADS) {
            int sy  = g / (SW / 4);
            int sx4 = (g - sy * (SW / 4)) * 4;
            int gy  = min(max(ty0 - R + sy, 0), HH - 1);
            int gofs = gy * WW + (tx0 - R + sx4);        // x is in-range & 16B aligned
            float4 a = *reinterpret_cast<const float4*>(im0 + gofs);
            float4 bb4 = *reinterpret_cast<const float4*>(im1 + gofs);
            float4 c = *reinterpret_cast<const float4*>(im2 + gofs);
            float4* dst = &smT[sy * PITCHT + sx4];
            dst[0] = make_float4(a.x, bb4.x, c.x, 0.f);
            dst[1] = make_float4(a.y, bb4.y, c.y, 0.f);
            dst[2] = make_float4(a.z, bb4.z, c.z, 0.f);
            dst[3] = make_float4(a.w, bb4.w, c.w, 0.f);
        }
    } else {
        // border-x blocks: scalar clamped staging
        #pragma unroll 1
        for (int g = tid; g < SH * SW; g += NTHREADS) {
            int sy = g / SW;
            int sx = g - sy * SW;
            int gy = min(max(ty0 - R + sy, 0), HH - 1);
            int gx = min(max(tx0 - R + sx, 0), WW - 1);
            int gofs = gy * WW + gx;
            smT[sy * PITCHT + sx] =
                make_float4(__ldg(im0 + gofs), __ldg(im1 + gofs), __ldg(im2 + gofs), 0.f);
        }
    }
    __syncthreads();

    // ---- Each thread: 4 consecutive pixels in one tile row ----
    const int row  = tid >> 4;              // 0..19
    const int col4 = (tid & 15) << 2;       // 0..60
    const int px   = tx0 + col4;
    const int py   = ty0 + row;
    const int pix  = py * WW + px;

    const float* flb = flow + (size_t)b * 2 * HWP;
    float4 fx4 = *reinterpret_cast<const float4*>(flb + pix);
    float4 fy4 = *reinterpret_cast<const float4*>(flb + HWP + pix);
    float fxs[4] = {fx4.x, fx4.y, fx4.z, fx4.w};
    float fys[4] = {fy4.x, fy4.y, fy4.z, fy4.w};

    float acc0[4], acc1[4], acc2[4];

    #pragma unroll
    for (int j = 0; j < 4; ++j) {
        float x = fminf(fmaxf((float)(px + j) + fxs[j], 0.0f), (float)(WW - 1));
        float y = fminf(fmaxf((float)py       + fys[j], 0.0f), (float)(HH - 1));
        float x0f = floorf(x);
        float y0f = floorf(y);
        float wx = x - x0f;
        float wy = y - y0f;
        int x0 = (int)x0f;
        int y0 = (int)y0f;
        int x1 = min(x0 + 1, WW - 1);
        int y1 = min(y0 + 1, HH - 1);

        int lx0 = x0 - (tx0 - R);
        int ly0 = y0 - (ty0 - R);
        int lx1 = x1 - (tx0 - R);
        int ly1 = y1 - (ty0 - R);

        bool inside = (lx0 >= 0) && (ly0 >= 0) && (lx1 < SW) && (ly1 < SH);
        if (inside) {
            float4 t00 = smT[ly0 * PITCHT + lx0];
            float4 t01 = smT[ly0 * PITCHT + lx1];
            float4 t10 = smT[ly1 * PITCHT + lx0];
            float4 t11 = smT[ly1 * PITCHT + lx1];
            float top, bot;
            top = t00.x + wx * (t01.x - t00.x);
            bot = t10.x + wx * (t11.x - t10.x);
            acc0[j] = top + wy * (bot - top);
            top = t00.y + wx * (t01.y - t00.y);
            bot = t10.y + wx * (t11.y - t10.y);
            acc1[j] = top + wy * (bot - top);
            top = t00.z + wx * (t01.z - t00.z);
            bot = t10.z + wx * (t11.z - t10.z);
            acc2[j] = top + wy * (bot - top);
        } else {
            // |flow| > ~6: essentially never for N(0,1); direct global gather
            int i00 = y0 * WW + x0;
            int i01 = y0 * WW + x1;
            int i10 = y1 * WW + x0;
            int i11 = y1 * WW + x1;
            float top, bot;
            top = __ldg(im0 + i00) + wx * (__ldg(im0 + i01) - __ldg(im0 + i00));
            bot = __ldg(im0 + i10) + wx * (__ldg(im0 + i11) - __ldg(im0 + i10));
            acc0[j] = top + wy * (bot - top);
            top = __ldg(im1 + i00) + wx * (__ldg(im1 + i01) - __ldg(im1 + i00));
            bot = __ldg(im1 + i10) + wx * (__ldg(im1 + i11) - __ldg(im1 + i10));
            acc1[j] = top + wy * (bot - top);
            top = __ldg(im2 + i00) + wx * (__ldg(im2 + i01) - __ldg(im2 + i00));
            bot = __ldg(im2 + i10) + wx * (__ldg(im2 + i11) - __ldg(im2 + i10));
            acc2[j] = top + wy * (bot - top);
        }
    }

    float* ob = out + (size_t)b * CC * HWP + pix;
    *reinterpret_cast<float4*>(ob)            = make_float4(acc0[0], acc0[1], acc0[2], acc0[3]);
    *reinterpret_cast<float4*>(ob + HWP)      = make_float4(acc1[0], acc1[1], acc1[2], acc1[3]);
    *reinterpret_cast<float4*>(ob + 2 * HWP)  = make_float4(acc2[0], acc2[1], acc2[2], acc2[3]);
}

extern "C" void kernel_launch(void* const* d_in, const int* in_sizes, int n_in,
                              void* d_out, int out_size) {
    const float* img  = (const float*)d_in[0];
    const float* flow = (const float*)d_in[1];
    float* out = (float*)d_out;

    dim3 grid(WW / TW, HH / TH, BB);   // (20, 36, 8) = 5760 blocks
    backwarp_texel<<<grid, NTHREADS>>>(img, flow, out);
}